// round 2
// baseline (speedup 1.0000x reference)
#include <cuda_runtime.h>
#include <math.h>

// Problem constants (fixed by the reference: B=16, R=2048, U=2048, D=1024)
#define B_ 16
#define R_ 2048
#define U_ 2048
#define D_ 1024

// Scratch (device globals: allocation-guard safe)
__device__ __align__(128) float g_S[(size_t)B_ * R_ * U_];  // scores / probs  (256 MiB)
__device__ __align__(128) float g_T[(size_t)B_ * R_ * D_];  // pre-LN buffer  (128 MiB)
__device__ __align__(128) float g_X[(size_t)B_ * R_ * D_];  // LN1 output     (128 MiB)
__device__ __align__(128) float g_H[(size_t)B_ * R_ * D_];  // FFN hidden     (128 MiB)

// ---------------------------------------------------------------------------
// Batched NT GEMM: C[b][m][n] = alpha * sum_k A[b][m][k] * B[b][n][k]
// A: [M,K] row-major (lda=K), B: [N,K] row-major (ldb=K), C: [M,N] (ldc=N)
// Tile 128x128x16, 256 threads, 8x8 per thread (split 4+4 halves).
// ---------------------------------------------------------------------------
__global__ __launch_bounds__(256, 2)
void gemm_nt_scores(const float* __restrict__ A, const float* __restrict__ Bm,
                    float* __restrict__ C,
                    int M, int N, int K,
                    long long sA, long long sB, long long sC,
                    float alpha)
{
    __shared__ float As[16][128];
    __shared__ float Bs[16][128];

    const float* Ab = A + (long long)blockIdx.z * sA;
    const float* Bb = Bm + (long long)blockIdx.z * sB;
    float*       Cb = C + (long long)blockIdx.z * sC;

    const int m0 = blockIdx.y * 128;
    const int n0 = blockIdx.x * 128;
    const int tid = threadIdx.x;
    const int tx = tid & 15;
    const int ty = tid >> 4;

    float acc[8][8];
#pragma unroll
    for (int i = 0; i < 8; i++)
#pragma unroll
        for (int j = 0; j < 8; j++) acc[i][j] = 0.f;

    for (int k0 = 0; k0 < K; k0 += 16) {
#pragma unroll
        for (int it = 0; it < 2; it++) {
            int s = tid + it * 256;      // 0..511 float4 slots
            int row = s >> 2;            // 0..127
            int c = (s & 3) << 2;        // 0,4,8,12
            float4 va = *(const float4*)(Ab + (long long)(m0 + row) * K + k0 + c);
            As[c + 0][row] = va.x; As[c + 1][row] = va.y;
            As[c + 2][row] = va.z; As[c + 3][row] = va.w;
            float4 vb = *(const float4*)(Bb + (long long)(n0 + row) * K + k0 + c);
            Bs[c + 0][row] = vb.x; Bs[c + 1][row] = vb.y;
            Bs[c + 2][row] = vb.z; Bs[c + 3][row] = vb.w;
        }
        __syncthreads();
#pragma unroll
        for (int k = 0; k < 16; k++) {
            float a[8], bv[8];
            *(float4*)&a[0]  = *(const float4*)&As[k][ty * 4];
            *(float4*)&a[4]  = *(const float4*)&As[k][64 + ty * 4];
            *(float4*)&bv[0] = *(const float4*)&Bs[k][tx * 4];
            *(float4*)&bv[4] = *(const float4*)&Bs[k][64 + tx * 4];
#pragma unroll
            for (int i = 0; i < 8; i++)
#pragma unroll
                for (int j = 0; j < 8; j++)
                    acc[i][j] = fmaf(a[i], bv[j], acc[i][j]);
        }
        __syncthreads();
    }

#pragma unroll
    for (int ih = 0; ih < 2; ih++)
#pragma unroll
        for (int i = 0; i < 4; i++) {
            int m = m0 + ih * 64 + ty * 4 + i;
#pragma unroll
            for (int jh = 0; jh < 2; jh++) {
                int n = n0 + jh * 64 + tx * 4;
                float4 v;
                v.x = acc[ih * 4 + i][jh * 4 + 0] * alpha;
                v.y = acc[ih * 4 + i][jh * 4 + 1] * alpha;
                v.z = acc[ih * 4 + i][jh * 4 + 2] * alpha;
                v.w = acc[ih * 4 + i][jh * 4 + 3] * alpha;
                *(float4*)(Cb + (long long)m * N + n) = v;
            }
        }
}

// ---------------------------------------------------------------------------
// Batched NN GEMM: C[b][m][n] = epi( sum_k A[b][m][k] * B[b][k][n] )
// EPI 0: + res[m][n]                 (PV + Q residual)
// EPI 1: relu(x + bias[n])           (FFN layer 1)
// EPI 2: x + bias[n] + res[m][n]     (FFN layer 2 + residual)
// ---------------------------------------------------------------------------
template <int EPI>
__global__ __launch_bounds__(256, 2)
void gemm_nn(const float* __restrict__ A, const float* __restrict__ Bm,
             float* __restrict__ C, const float* __restrict__ res,
             const float* __restrict__ bias,
             int M, int N, int K,
             long long sA, long long sB, long long sC, long long sRes)
{
    __shared__ float As[16][128];
    __shared__ float Bs[16][128];

    const float* Ab = A + (long long)blockIdx.z * sA;
    const float* Bb = Bm + (long long)blockIdx.z * sB;
    float*       Cb = C + (long long)blockIdx.z * sC;
    const float* Rb = (EPI != 1) ? (res + (long long)blockIdx.z * sRes) : res;

    const int m0 = blockIdx.y * 128;
    const int n0 = blockIdx.x * 128;
    const int tid = threadIdx.x;
    const int tx = tid & 15;
    const int ty = tid >> 4;

    float acc[8][8];
#pragma unroll
    for (int i = 0; i < 8; i++)
#pragma unroll
        for (int j = 0; j < 8; j++) acc[i][j] = 0.f;

    for (int k0 = 0; k0 < K; k0 += 16) {
#pragma unroll
        for (int it = 0; it < 2; it++) {
            int s = tid + it * 256;
            {   // A tile (transposed store)
                int row = s >> 2;
                int c = (s & 3) << 2;
                float4 va = *(const float4*)(Ab + (long long)(m0 + row) * K + k0 + c);
                As[c + 0][row] = va.x; As[c + 1][row] = va.y;
                As[c + 2][row] = va.z; As[c + 3][row] = va.w;
            }
            {   // B tile (direct store, coalesced along n)
                int row = s >> 5;            // 0..15
                int c = (s & 31) << 2;       // 0..124
                *(float4*)&Bs[row][c] =
                    *(const float4*)(Bb + (long long)(k0 + row) * N + n0 + c);
            }
        }
        __syncthreads();
#pragma unroll
        for (int k = 0; k < 16; k++) {
            float a[8], bv[8];
            *(float4*)&a[0]  = *(const float4*)&As[k][ty * 4];
            *(float4*)&a[4]  = *(const float4*)&As[k][64 + ty * 4];
            *(float4*)&bv[0] = *(const float4*)&Bs[k][tx * 4];
            *(float4*)&bv[4] = *(const float4*)&Bs[k][64 + tx * 4];
#pragma unroll
            for (int i = 0; i < 8; i++)
#pragma unroll
                for (int j = 0; j < 8; j++)
                    acc[i][j] = fmaf(a[i], bv[j], acc[i][j]);
        }
        __syncthreads();
    }

#pragma unroll
    for (int ih = 0; ih < 2; ih++)
#pragma unroll
        for (int i = 0; i < 4; i++) {
            int m = m0 + ih * 64 + ty * 4 + i;
#pragma unroll
            for (int jh = 0; jh < 2; jh++) {
                int n = n0 + jh * 64 + tx * 4;
                float4 v;
                v.x = acc[ih * 4 + i][jh * 4 + 0];
                v.y = acc[ih * 4 + i][jh * 4 + 1];
                v.z = acc[ih * 4 + i][jh * 4 + 2];
                v.w = acc[ih * 4 + i][jh * 4 + 3];
                if (EPI == 0) {
                    float4 r = *(const float4*)(Rb + (long long)m * N + n);
                    v.x += r.x; v.y += r.y; v.z += r.z; v.w += r.w;
                } else if (EPI == 1) {
                    float4 bb = *(const float4*)(bias + n);
                    v.x = fmaxf(v.x + bb.x, 0.f);
                    v.y = fmaxf(v.y + bb.y, 0.f);
                    v.z = fmaxf(v.z + bb.z, 0.f);
                    v.w = fmaxf(v.w + bb.w, 0.f);
                } else {
                    float4 bb = *(const float4*)(bias + n);
                    float4 r = *(const float4*)(Rb + (long long)m * N + n);
                    v.x += bb.x + r.x; v.y += bb.y + r.y;
                    v.z += bb.z + r.z; v.w += bb.w + r.w;
                }
                *(float4*)(Cb + (long long)m * N + n) = v;
            }
        }
}

// ---------------------------------------------------------------------------
// Row softmax over U=2048 elements. One CTA (256 threads) per row, in place.
// ---------------------------------------------------------------------------
__global__ void softmax_rows(float* __restrict__ S)
{
    float* p = S + (long long)blockIdx.x * U_;
    const int tid = threadIdx.x;
    const int lane = tid & 31;
    const int wid = tid >> 5;
    __shared__ float red[8];

    float4 v0 = ((const float4*)p)[tid];
    float4 v1 = ((const float4*)p)[tid + 256];

    // --- max ---
    float m = fmaxf(fmaxf(fmaxf(v0.x, v0.y), fmaxf(v0.z, v0.w)),
                    fmaxf(fmaxf(v1.x, v1.y), fmaxf(v1.z, v1.w)));
#pragma unroll
    for (int o = 16; o > 0; o >>= 1) m = fmaxf(m, __shfl_xor_sync(0xffffffffu, m, o));
    if (lane == 0) red[wid] = m;
    __syncthreads();
    if (tid == 0) {
        float t = red[0];
#pragma unroll
        for (int i = 1; i < 8; i++) t = fmaxf(t, red[i]);
        red[0] = t;
    }
    __syncthreads();
    m = red[0];
    __syncthreads();

    // --- exp + sum ---
    v0.x = __expf(v0.x - m); v0.y = __expf(v0.y - m);
    v0.z = __expf(v0.z - m); v0.w = __expf(v0.w - m);
    v1.x = __expf(v1.x - m); v1.y = __expf(v1.y - m);
    v1.z = __expf(v1.z - m); v1.w = __expf(v1.w - m);
    float s = v0.x + v0.y + v0.z + v0.w + v1.x + v1.y + v1.z + v1.w;
#pragma unroll
    for (int o = 16; o > 0; o >>= 1) s += __shfl_xor_sync(0xffffffffu, s, o);
    if (lane == 0) red[wid] = s;
    __syncthreads();
    if (tid == 0) {
        float t = 0.f;
#pragma unroll
        for (int i = 0; i < 8; i++) t += red[i];
        red[0] = t;
    }
    __syncthreads();
    const float inv = 1.f / red[0];

    v0.x *= inv; v0.y *= inv; v0.z *= inv; v0.w *= inv;
    v1.x *= inv; v1.y *= inv; v1.z *= inv; v1.w *= inv;
    ((float4*)p)[tid] = v0;
    ((float4*)p)[tid + 256] = v1;
}

// ---------------------------------------------------------------------------
// Row LayerNorm over D=1024. One CTA (256 threads) per row. Two-pass stats.
// ---------------------------------------------------------------------------
__global__ void layernorm_rows(const float* __restrict__ in, float* __restrict__ out,
                               const float* __restrict__ gamma,
                               const float* __restrict__ beta)
{
    const long long row = (long long)blockIdx.x * D_;
    const int tid = threadIdx.x;
    const int lane = tid & 31;
    const int wid = tid >> 5;
    __shared__ float red[8];

    float4 v = ((const float4*)(in + row))[tid];

    // mean
    float s = v.x + v.y + v.z + v.w;
#pragma unroll
    for (int o = 16; o > 0; o >>= 1) s += __shfl_xor_sync(0xffffffffu, s, o);
    if (lane == 0) red[wid] = s;
    __syncthreads();
    if (tid == 0) {
        float t = 0.f;
#pragma unroll
        for (int i = 0; i < 8; i++) t += red[i];
        red[0] = t;
    }
    __syncthreads();
    const float mean = red[0] * (1.f / D_);
    __syncthreads();

    // variance (two-pass for accuracy)
    float dx = v.x - mean, dy = v.y - mean, dz = v.z - mean, dw = v.w - mean;
    float sq = dx * dx + dy * dy + dz * dz + dw * dw;
#pragma unroll
    for (int o = 16; o > 0; o >>= 1) sq += __shfl_xor_sync(0xffffffffu, sq, o);
    if (lane == 0) red[wid] = sq;
    __syncthreads();
    if (tid == 0) {
        float t = 0.f;
#pragma unroll
        for (int i = 0; i < 8; i++) t += red[i];
        red[0] = t;
    }
    __syncthreads();
    const float var = red[0] * (1.f / D_);
    const float rstd = rsqrtf(var + 1e-6f);

    float4 g = ((const float4*)gamma)[tid];
    float4 bt = ((const float4*)beta)[tid];
    float4 o;
    o.x = dx * rstd * g.x + bt.x;
    o.y = dy * rstd * g.y + bt.y;
    o.z = dz * rstd * g.z + bt.z;
    o.w = dw * rstd * g.w + bt.w;
    ((float4*)(out + row))[tid] = o;
}

// ---------------------------------------------------------------------------
// Launch: scores -> softmax -> PV(+Q) -> LN -> FFN1(relu) -> FFN2(+X) -> LN
// ---------------------------------------------------------------------------
extern "C" void kernel_launch(void* const* d_in, const int* in_sizes, int n_in,
                              void* d_out, int out_size)
{
    const float* Q     = (const float*)d_in[0];
    const float* Kin   = (const float*)d_in[1];
    const float* V     = (const float*)d_in[2];
    const float* W1    = (const float*)d_in[3];
    const float* b1    = (const float*)d_in[4];
    const float* W2    = (const float*)d_in[5];
    const float* b2    = (const float*)d_in[6];
    const float* gamma = (const float*)d_in[7];
    const float* beta  = (const float*)d_in[8];
    float* out = (float*)d_out;

    float *S, *T, *X, *H;
    cudaGetSymbolAddress((void**)&S, g_S);
    cudaGetSymbolAddress((void**)&T, g_T);
    cudaGetSymbolAddress((void**)&X, g_X);
    cudaGetSymbolAddress((void**)&H, g_H);

    const float alpha = 1.0f / sqrtf((float)D_ + 1e-8f);
    dim3 blk(256);

    // 1) S = Q @ K^T / scale   (batched NT)
    gemm_nt_scores<<<dim3(U_ / 128, R_ / 128, B_), blk>>>(
        Q, Kin, S, R_, U_, D_,
        (long long)R_ * D_, (long long)U_ * D_, (long long)R_ * U_, alpha);

    // 2) softmax rows
    softmax_rows<<<B_ * R_, 256>>>(S);

    // 3) T = S @ V + Q   (batched NN, residual epilogue)
    gemm_nn<0><<<dim3(D_ / 128, R_ / 128, B_), blk>>>(
        S, V, T, Q, nullptr, R_, D_, U_,
        (long long)R_ * U_, (long long)U_ * D_, (long long)R_ * D_, (long long)R_ * D_);

    // 4) X = LN(T)
    layernorm_rows<<<B_ * R_, 256>>>(T, X, gamma, beta);

    // 5) H = relu(X @ W1 + b1)
    gemm_nn<1><<<dim3(D_ / 128, (B_ * R_) / 128, 1), blk>>>(
        X, W1, H, nullptr, b1, B_ * R_, D_, D_, 0, 0, 0, 0);

    // 6) T = H @ W2 + b2 + X
    gemm_nn<2><<<dim3(D_ / 128, (B_ * R_) / 128, 1), blk>>>(
        H, W2, T, X, b2, B_ * R_, D_, D_, 0, 0, 0, 0);

    // 7) out = LN(T)
    layernorm_rows<<<B_ * R_, 256>>>(T, out, gamma, beta);
}

// round 3
// speedup vs baseline: 2.9025x; 2.9025x over previous
#include <cuda_runtime.h>
#include <math.h>
#include <stdint.h>

// Problem constants (fixed by the reference: B=16, R=2048, U=2048, D=1024)
#define B_ 16
#define R_ 2048
#define U_ 2048
#define D_ 1024

// Scratch (device globals: allocation-guard safe)
__device__ __align__(128) float g_S[(size_t)B_ * R_ * U_];  // scores / probs  (256 MiB)
__device__ __align__(128) float g_T[(size_t)B_ * R_ * D_];  // pre-LN buffer
__device__ __align__(128) float g_X[(size_t)B_ * R_ * D_];  // LN1 output
__device__ __align__(128) float g_H[(size_t)B_ * R_ * D_];  // FFN hidden

// ---------------------------------------------------------------------------
// tf32 helpers
// ---------------------------------------------------------------------------
__device__ __forceinline__ uint32_t f2tf(float x) {
    uint32_t r;
    asm("cvt.rna.tf32.f32 %0, %1;" : "=r"(r) : "f"(x));
    return r;
}

__device__ __forceinline__ void mma_tf32(float* c,
                                         uint32_t a0, uint32_t a1, uint32_t a2, uint32_t a3,
                                         uint32_t b0, uint32_t b1) {
    asm volatile(
        "mma.sync.aligned.m16n8k8.row.col.f32.tf32.tf32.f32 "
        "{%0,%1,%2,%3}, {%4,%5,%6,%7}, {%8,%9}, {%0,%1,%2,%3};"
        : "+f"(c[0]), "+f"(c[1]), "+f"(c[2]), "+f"(c[3])
        : "r"(a0), "r"(a1), "r"(a2), "r"(a3), "r"(b0), "r"(b1));
}

__device__ __forceinline__ void cp16(uint32_t dst_smem, const void* src) {
    asm volatile("cp.async.cg.shared.global [%0], [%1], 16;" :: "r"(dst_smem), "l"(src));
}
__device__ __forceinline__ void cp_commit() { asm volatile("cp.async.commit_group;"); }

// ---------------------------------------------------------------------------
// tf32 GEMM, CTA tile 128x128, KTILE=32, 2-stage cp.async pipeline.
// BNT=1: B is [N,K] row-major (NT, scores).  BNT=0: B is [K,N] row-major (NN).
// EPI 0: C = alpha * acc                      (scores)
// EPI 1: C = acc + res                        (PV + Q residual)
// EPI 2: C = relu(acc + bias)                 (FFN1)
// EPI 3: C = acc + bias + res                 (FFN2 + residual)
// Smem layouts (per stage, 4096 floats each):
//   A:  (m,k): m*32 + ((k/4) ^ (m&7))*4 + k%4           [also B when BNT=1, with n]
//   B NN: (k,n): k*128 + (((n/4) ^ ((k&3)*2))*4) + n%4
// Both are bank-conflict-free for all mma fragment loads (verified per-lane).
// ---------------------------------------------------------------------------
template <int BNT, int EPI>
__global__ __launch_bounds__(256)
void gemm_tf32(const float* __restrict__ A, const float* __restrict__ Bm,
               float* __restrict__ C, const float* __restrict__ res,
               const float* __restrict__ bias,
               int M, int N, int K, int lda, int ldb,
               long long sA, long long sB, long long sC, long long sRes,
               float alpha)
{
    extern __shared__ float sm[];
    float* As = sm;           // 2 stages x 4096 floats
    float* Bs = sm + 8192;    // 2 stages x 4096 floats

    const float* Ab = A + (long long)blockIdx.z * sA;
    const float* Bb = Bm + (long long)blockIdx.z * sB;
    float*       Cb = C + (long long)blockIdx.z * sC;
    const float* Rb = res ? (res + (long long)blockIdx.z * sRes) : res;

    const int m0 = blockIdx.y * 128;
    const int n0 = blockIdx.x * 128;
    const int tid = threadIdx.x;
    const int lane = tid & 31;
    const int wid = tid >> 5;
    const int warp_m = wid & 3;   // 4 warps along M (32 rows each)
    const int warp_n = wid >> 2;  // 2 warps along N (64 cols each)

    uint32_t As_u = (uint32_t)__cvta_generic_to_shared(As);
    uint32_t Bs_u = (uint32_t)__cvta_generic_to_shared(Bs);

    float acc[2][8][4];
#pragma unroll
    for (int i = 0; i < 2; i++)
#pragma unroll
        for (int j = 0; j < 8; j++)
#pragma unroll
            for (int l = 0; l < 4; l++) acc[i][j][l] = 0.f;

    const int KT = K >> 5;  // K / 32

    // ---- prefetch one stage ----
    auto prefetch = [&](int kt, int s) {
#pragma unroll
        for (int i = 0; i < 4; i++) {
            int idx = tid + i * 256;           // 0..1023
            int m = idx >> 3, kq = idx & 7;    // 8 quads of k per row
            int sw = kq ^ (m & 7);
            cp16(As_u + (uint32_t)(s * 4096 + m * 32 + sw * 4) * 4,
                 Ab + (long long)(m0 + m) * lda + kt * 32 + kq * 4);
        }
        if (BNT) {
#pragma unroll
            for (int i = 0; i < 4; i++) {
                int idx = tid + i * 256;
                int n = idx >> 3, kq = idx & 7;
                int sw = kq ^ (n & 7);
                cp16(Bs_u + (uint32_t)(s * 4096 + n * 32 + sw * 4) * 4,
                     Bb + (long long)(n0 + n) * ldb + kt * 32 + kq * 4);
            }
        } else {
#pragma unroll
            for (int i = 0; i < 4; i++) {
                int idx = tid + i * 256;
                int k = idx >> 5, nq = idx & 31;   // 32 quads of n per k-row
                int sw = nq ^ ((k & 3) * 2);
                cp16(Bs_u + (uint32_t)(s * 4096 + k * 128 + sw * 4) * 4,
                     Bb + (long long)(kt * 32 + k) * ldb + n0 + nq * 4);
            }
        }
    };

    prefetch(0, 0);
    cp_commit();

    for (int kt = 0; kt < KT; ++kt) {
        const int s = kt & 1;
        if (kt + 1 < KT) {
            prefetch(kt + 1, (kt + 1) & 1);
            cp_commit();
            asm volatile("cp.async.wait_group 1;");
        } else {
            asm volatile("cp.async.wait_group 0;");
        }
        __syncthreads();

#pragma unroll
        for (int ksub = 0; ksub < 4; ++ksub) {
            // B fragments for all 8 n-tiles
            uint32_t bf[8][2];
#pragma unroll
            for (int nt = 0; nt < 8; nt++) {
                if (BNT) {
                    int n = warp_n * 64 + nt * 8 + (lane >> 2);
                    int base = s * 4096 + n * 32;
                    int c0 = ((ksub * 2) ^ (n & 7)) * 4 + (lane & 3);
                    int c1 = ((ksub * 2 + 1) ^ (n & 7)) * 4 + (lane & 3);
                    bf[nt][0] = f2tf(Bs[base + c0]);
                    bf[nt][1] = f2tf(Bs[base + c1]);
                } else {
                    int k = ksub * 8 + (lane & 3);
                    int n = warp_n * 64 + nt * 8 + (lane >> 2);
                    int off = s * 4096 + k * 128 +
                              (((n >> 2) ^ ((k & 3) * 2)) * 4) + (n & 3);
                    bf[nt][0] = f2tf(Bs[off]);
                    bf[nt][1] = f2tf(Bs[off + 512]);  // k+4 row, same swizzle
                }
            }
            // A fragments, 2 m-tiles
#pragma unroll
            for (int mt = 0; mt < 2; mt++) {
                int m = warp_m * 32 + mt * 16 + (lane >> 2);
                int base = s * 4096 + m * 32;
                int c0 = ((ksub * 2) ^ (m & 7)) * 4 + (lane & 3);
                int c1 = ((ksub * 2 + 1) ^ (m & 7)) * 4 + (lane & 3);
                uint32_t a0 = f2tf(As[base + c0]);
                uint32_t a1 = f2tf(As[base + 256 + c0]);   // m+8 (8*32)
                uint32_t a2 = f2tf(As[base + c1]);
                uint32_t a3 = f2tf(As[base + 256 + c1]);
#pragma unroll
                for (int nt = 0; nt < 8; nt++)
                    mma_tf32(acc[mt][nt], a0, a1, a2, a3, bf[nt][0], bf[nt][1]);
            }
        }
        __syncthreads();
    }

    // ---- epilogue ----
#pragma unroll
    for (int mt = 0; mt < 2; mt++) {
        int r0 = m0 + warp_m * 32 + mt * 16 + (lane >> 2);
#pragma unroll
        for (int nt = 0; nt < 8; nt++) {
            int cc = n0 + warp_n * 64 + nt * 8 + (lane & 3) * 2;
            float v0 = acc[mt][nt][0], v1 = acc[mt][nt][1];
            float v2 = acc[mt][nt][2], v3 = acc[mt][nt][3];
            if (EPI == 0) {
                v0 *= alpha; v1 *= alpha; v2 *= alpha; v3 *= alpha;
            } else if (EPI == 1) {
                const float2 ra = *(const float2*)(Rb + (long long)r0 * N + cc);
                const float2 rb = *(const float2*)(Rb + (long long)(r0 + 8) * N + cc);
                v0 += ra.x; v1 += ra.y; v2 += rb.x; v3 += rb.y;
            } else if (EPI == 2) {
                const float2 bb = *(const float2*)(bias + cc);
                v0 = fmaxf(v0 + bb.x, 0.f); v1 = fmaxf(v1 + bb.y, 0.f);
                v2 = fmaxf(v2 + bb.x, 0.f); v3 = fmaxf(v3 + bb.y, 0.f);
            } else {
                const float2 bb = *(const float2*)(bias + cc);
                const float2 ra = *(const float2*)(Rb + (long long)r0 * N + cc);
                const float2 rb = *(const float2*)(Rb + (long long)(r0 + 8) * N + cc);
                v0 += bb.x + ra.x; v1 += bb.y + ra.y;
                v2 += bb.x + rb.x; v3 += bb.y + rb.y;
            }
            *(float2*)(Cb + (long long)r0 * N + cc) = make_float2(v0, v1);
            *(float2*)(Cb + (long long)(r0 + 8) * N + cc) = make_float2(v2, v3);
        }
    }
}

// ---------------------------------------------------------------------------
// Row softmax over U=2048 elements. One CTA (256 threads) per row, in place.
// ---------------------------------------------------------------------------
__global__ void softmax_rows(float* __restrict__ S)
{
    float* p = S + (long long)blockIdx.x * U_;
    const int tid = threadIdx.x;
    const int lane = tid & 31;
    const int wid = tid >> 5;
    __shared__ float red[8];

    float4 v0 = ((const float4*)p)[tid];
    float4 v1 = ((const float4*)p)[tid + 256];

    float m = fmaxf(fmaxf(fmaxf(v0.x, v0.y), fmaxf(v0.z, v0.w)),
                    fmaxf(fmaxf(v1.x, v1.y), fmaxf(v1.z, v1.w)));
#pragma unroll
    for (int o = 16; o > 0; o >>= 1) m = fmaxf(m, __shfl_xor_sync(0xffffffffu, m, o));
    if (lane == 0) red[wid] = m;
    __syncthreads();
    if (tid == 0) {
        float t = red[0];
#pragma unroll
        for (int i = 1; i < 8; i++) t = fmaxf(t, red[i]);
        red[0] = t;
    }
    __syncthreads();
    m = red[0];
    __syncthreads();

    v0.x = __expf(v0.x - m); v0.y = __expf(v0.y - m);
    v0.z = __expf(v0.z - m); v0.w = __expf(v0.w - m);
    v1.x = __expf(v1.x - m); v1.y = __expf(v1.y - m);
    v1.z = __expf(v1.z - m); v1.w = __expf(v1.w - m);
    float sum = v0.x + v0.y + v0.z + v0.w + v1.x + v1.y + v1.z + v1.w;
#pragma unroll
    for (int o = 16; o > 0; o >>= 1) sum += __shfl_xor_sync(0xffffffffu, sum, o);
    if (lane == 0) red[wid] = sum;
    __syncthreads();
    if (tid == 0) {
        float t = 0.f;
#pragma unroll
        for (int i = 0; i < 8; i++) t += red[i];
        red[0] = t;
    }
    __syncthreads();
    const float inv = 1.f / red[0];

    v0.x *= inv; v0.y *= inv; v0.z *= inv; v0.w *= inv;
    v1.x *= inv; v1.y *= inv; v1.z *= inv; v1.w *= inv;
    ((float4*)p)[tid] = v0;
    ((float4*)p)[tid + 256] = v1;
}

// ---------------------------------------------------------------------------
// Row LayerNorm over D=1024. One CTA (256 threads) per row. Two-pass stats.
// ---------------------------------------------------------------------------
__global__ void layernorm_rows(const float* __restrict__ in, float* __restrict__ out,
                               const float* __restrict__ gamma,
                               const float* __restrict__ beta)
{
    const long long row = (long long)blockIdx.x * D_;
    const int tid = threadIdx.x;
    const int lane = tid & 31;
    const int wid = tid >> 5;
    __shared__ float red[8];

    float4 v = ((const float4*)(in + row))[tid];

    float s = v.x + v.y + v.z + v.w;
#pragma unroll
    for (int o = 16; o > 0; o >>= 1) s += __shfl_xor_sync(0xffffffffu, s, o);
    if (lane == 0) red[wid] = s;
    __syncthreads();
    if (tid == 0) {
        float t = 0.f;
#pragma unroll
        for (int i = 0; i < 8; i++) t += red[i];
        red[0] = t;
    }
    __syncthreads();
    const float mean = red[0] * (1.f / D_);
    __syncthreads();

    float dx = v.x - mean, dy = v.y - mean, dz = v.z - mean, dw = v.w - mean;
    float sq = dx * dx + dy * dy + dz * dz + dw * dw;
#pragma unroll
    for (int o = 16; o > 0; o >>= 1) sq += __shfl_xor_sync(0xffffffffu, sq, o);
    if (lane == 0) red[wid] = sq;
    __syncthreads();
    if (tid == 0) {
        float t = 0.f;
#pragma unroll
        for (int i = 0; i < 8; i++) t += red[i];
        red[0] = t;
    }
    __syncthreads();
    const float var = red[0] * (1.f / D_);
    const float rstd = rsqrtf(var + 1e-6f);

    float4 g = ((const float4*)gamma)[tid];
    float4 bt = ((const float4*)beta)[tid];
    float4 o;
    o.x = dx * rstd * g.x + bt.x;
    o.y = dy * rstd * g.y + bt.y;
    o.z = dz * rstd * g.z + bt.z;
    o.w = dw * rstd * g.w + bt.w;
    ((float4*)(out + row))[tid] = o;
}

// ---------------------------------------------------------------------------
// Launch: scores -> softmax -> PV(+Q) -> LN -> FFN1(relu) -> FFN2(+X) -> LN
// ---------------------------------------------------------------------------
extern "C" void kernel_launch(void* const* d_in, const int* in_sizes, int n_in,
                              void* d_out, int out_size)
{
    const float* Q     = (const float*)d_in[0];
    const float* Kin   = (const float*)d_in[1];
    const float* V     = (const float*)d_in[2];
    const float* W1    = (const float*)d_in[3];
    const float* b1    = (const float*)d_in[4];
    const float* W2    = (const float*)d_in[5];
    const float* b2    = (const float*)d_in[6];
    const float* gamma = (const float*)d_in[7];
    const float* beta  = (const float*)d_in[8];
    float* out = (float*)d_out;

    float *S, *T, *X, *H;
    cudaGetSymbolAddress((void**)&S, g_S);
    cudaGetSymbolAddress((void**)&T, g_T);
    cudaGetSymbolAddress((void**)&X, g_X);
    cudaGetSymbolAddress((void**)&H, g_H);

    const float alpha = 1.0f / sqrtf((float)D_ + 1e-8f);
    const size_t shm = 65536;  // 2-stage * (16KB A + 16KB B)
    dim3 blk(256);

    cudaFuncSetAttribute(gemm_tf32<1, 0>, cudaFuncAttributeMaxDynamicSharedMemorySize, (int)shm);
    cudaFuncSetAttribute(gemm_tf32<0, 1>, cudaFuncAttributeMaxDynamicSharedMemorySize, (int)shm);
    cudaFuncSetAttribute(gemm_tf32<0, 2>, cudaFuncAttributeMaxDynamicSharedMemorySize, (int)shm);
    cudaFuncSetAttribute(gemm_tf32<0, 3>, cudaFuncAttributeMaxDynamicSharedMemorySize, (int)shm);

    // 1) S = Q @ K^T / scale   (batched NT)
    gemm_tf32<1, 0><<<dim3(U_ / 128, R_ / 128, B_), blk, shm>>>(
        Q, Kin, S, nullptr, nullptr, R_, U_, D_, D_, D_,
        (long long)R_ * D_, (long long)U_ * D_, (long long)R_ * U_, 0, alpha);

    // 2) softmax rows
    softmax_rows<<<B_ * R_, 256>>>(S);

    // 3) T = S @ V + Q   (batched NN, residual epilogue)
    gemm_tf32<0, 1><<<dim3(D_ / 128, R_ / 128, B_), blk, shm>>>(
        S, V, T, Q, nullptr, R_, D_, U_, U_, D_,
        (long long)R_ * U_, (long long)U_ * D_, (long long)R_ * D_, (long long)R_ * D_, 1.f);

    // 4) X = LN(T)
    layernorm_rows<<<B_ * R_, 256>>>(T, X, gamma, beta);

    // 5) H = relu(X @ W1 + b1)
    gemm_tf32<0, 2><<<dim3(D_ / 128, (B_ * R_) / 128, 1), blk, shm>>>(
        X, W1, H, nullptr, b1, B_ * R_, D_, D_, D_, D_, 0, 0, 0, 0, 1.f);

    // 6) T = H @ W2 + b2 + X
    gemm_tf32<0, 3><<<dim3(D_ / 128, (B_ * R_) / 128, 1), blk, shm>>>(
        H, W2, T, X, b2, B_ * R_, D_, D_, D_, D_, 0, 0, 0, 0, 1.f);

    // 7) out = LN(T)
    layernorm_rows<<<B_ * R_, 256>>>(T, out, gamma, beta);
}

// round 5
// speedup vs baseline: 3.4647x; 1.1937x over previous
#include <cuda_runtime.h>
#include <math.h>
#include <stdint.h>

// Problem constants (fixed by the reference: B=16, R=2048, U=2048, D=1024)
#define B_ 16
#define R_ 2048
#define U_ 2048
#define D_ 1024

// Scratch (device globals: allocation-guard safe)
__device__ __align__(128) float g_S[(size_t)B_ * R_ * U_];   // scores / probs (256 MiB)
__device__ __align__(128) float g_T[(size_t)B_ * R_ * D_];   // pre-LN buffer
__device__ __align__(128) float g_X[(size_t)B_ * R_ * D_];   // LN1 output (full fp32)
__device__ __align__(128) float g_Xr[(size_t)B_ * R_ * D_];  // LN1 output (tf32-rounded)
__device__ __align__(128) float g_H[(size_t)B_ * R_ * D_];   // FFN hidden (tf32-rounded)
__device__ __align__(128) float g_Qr[(size_t)B_ * R_ * D_];  // tf32-rounded Q
__device__ __align__(128) float g_Kr[(size_t)B_ * U_ * D_];  // tf32-rounded K
__device__ __align__(128) float g_Vr[(size_t)B_ * U_ * D_];  // tf32-rounded V
__device__ __align__(128) float g_W1r[(size_t)D_ * D_];
__device__ __align__(128) float g_W2r[(size_t)D_ * D_];

// ---------------------------------------------------------------------------
// tf32 helpers
// ---------------------------------------------------------------------------
__device__ __forceinline__ uint32_t f2tf(float x) {
    uint32_t r;
    asm("cvt.rna.tf32.f32 %0, %1;" : "=r"(r) : "f"(x));
    return r;
}
__device__ __forceinline__ float roundtf(float x) { return __uint_as_float(f2tf(x)); }

__device__ __forceinline__ void mma_tf32(float* c,
                                         uint32_t a0, uint32_t a1, uint32_t a2, uint32_t a3,
                                         uint32_t b0, uint32_t b1) {
    asm volatile(
        "mma.sync.aligned.m16n8k8.row.col.f32.tf32.tf32.f32 "
        "{%0,%1,%2,%3}, {%4,%5,%6,%7}, {%8,%9}, {%0,%1,%2,%3};"
        : "+f"(c[0]), "+f"(c[1]), "+f"(c[2]), "+f"(c[3])
        : "r"(a0), "r"(a1), "r"(a2), "r"(a3), "r"(b0), "r"(b1));
}

__device__ __forceinline__ void cp16(uint32_t dst_smem, const void* src) {
    asm volatile("cp.async.cg.shared.global [%0], [%1], 16;" :: "r"(dst_smem), "l"(src));
}
__device__ __forceinline__ void cp_commit() { asm volatile("cp.async.commit_group;"); }

// ---------------------------------------------------------------------------
// Elementwise tf32 rounding pass (operands pre-rounded once, no in-loop cvt)
// ---------------------------------------------------------------------------
__global__ void round_tf32_kernel(const float* __restrict__ in, float* __restrict__ out)
{
    long long i = (long long)blockIdx.x * 256 + threadIdx.x;
    float4 v = ((const float4*)in)[i];
    v.x = roundtf(v.x); v.y = roundtf(v.y);
    v.z = roundtf(v.z); v.w = roundtf(v.w);
    ((float4*)out)[i] = v;
}

// ---------------------------------------------------------------------------
// tf32 GEMM, CTA tile 128x128, KTILE=32, 2-stage cp.async pipeline.
// 128 threads = 4 warps, warp tile 64x64 (2x2 warp grid), 4 mt x 8 nt mmas.
// Inputs must already be tf32-rounded; fragments are raw fp32 bit patterns.
// BNT=1: B is [N,K] row-major (NT).  BNT=0: B is [K,N] row-major (NN).
// EPI 0: C = alpha * acc                      (scores)
// EPI 1: C = acc + res                        (PV + Q residual)
// EPI 2: C = roundtf(relu(acc + bias))        (FFN1 -> rounded H)
// EPI 3: C = acc + bias + res                 (FFN2 + residual)
// Smem layouts (per stage, 4096 floats each):
//   A / B(NT): (r,k): r*32 + ((k/4) ^ (r&7))*4 + k%4
//   B(NN):     (k,n): k*128 + (((n/4) ^ ((k&3)*2))*4) + n%4
// ---------------------------------------------------------------------------
template <int BNT, int EPI>
__global__ __launch_bounds__(128)
void gemm_tf32(const float* __restrict__ A, const float* __restrict__ Bm,
               float* __restrict__ C, const float* __restrict__ res,
               const float* __restrict__ bias,
               int M, int N, int K, int lda, int ldb,
               long long sA, long long sB, long long sC, long long sRes,
               float alpha)
{
    extern __shared__ float sm[];
    float* As = sm;           // 2 stages x 4096 floats
    float* Bs = sm + 8192;    // 2 stages x 4096 floats

    const float* Ab = A + (long long)blockIdx.z * sA;
    const float* Bb = Bm + (long long)blockIdx.z * sB;
    float*       Cb = C + (long long)blockIdx.z * sC;
    const float* Rb = res ? (res + (long long)blockIdx.z * sRes) : res;

    const int m0 = blockIdx.y * 128;
    const int n0 = blockIdx.x * 128;
    const int tid = threadIdx.x;
    const int lane = tid & 31;
    const int wid = tid >> 5;
    const int warp_m = wid & 1;   // 2 warps along M (64 rows each)
    const int warp_n = wid >> 1;  // 2 warps along N (64 cols each)

    uint32_t As_u = (uint32_t)__cvta_generic_to_shared(As);
    uint32_t Bs_u = (uint32_t)__cvta_generic_to_shared(Bs);

    float acc[4][8][4];
#pragma unroll
    for (int i = 0; i < 4; i++)
#pragma unroll
        for (int j = 0; j < 8; j++)
#pragma unroll
            for (int l = 0; l < 4; l++) acc[i][j][l] = 0.f;

    const int KT = K >> 5;  // K / 32

    auto prefetch = [&](int kt, int s) {
#pragma unroll
        for (int i = 0; i < 8; i++) {
            int idx = tid + i * 128;           // 0..1023 float4 slots
            int m = idx >> 3, kq = idx & 7;
            int sw = kq ^ (m & 7);
            cp16(As_u + (uint32_t)(s * 4096 + m * 32 + sw * 4) * 4,
                 Ab + (long long)(m0 + m) * lda + kt * 32 + kq * 4);
        }
        if (BNT) {
#pragma unroll
            for (int i = 0; i < 8; i++) {
                int idx = tid + i * 128;
                int n = idx >> 3, kq = idx & 7;
                int sw = kq ^ (n & 7);
                cp16(Bs_u + (uint32_t)(s * 4096 + n * 32 + sw * 4) * 4,
                     Bb + (long long)(n0 + n) * ldb + kt * 32 + kq * 4);
            }
        } else {
#pragma unroll
            for (int i = 0; i < 8; i++) {
                int idx = tid + i * 128;
                int k = idx >> 5, nq = idx & 31;
                int sw = nq ^ ((k & 3) * 2);
                cp16(Bs_u + (uint32_t)(s * 4096 + k * 128 + sw * 4) * 4,
                     Bb + (long long)(kt * 32 + k) * ldb + n0 + nq * 4);
            }
        }
    };

    prefetch(0, 0);
    cp_commit();

    for (int kt = 0; kt < KT; ++kt) {
        const int s = kt & 1;
        if (kt + 1 < KT) {
            prefetch(kt + 1, (kt + 1) & 1);
            cp_commit();
            asm volatile("cp.async.wait_group 1;");
        } else {
            asm volatile("cp.async.wait_group 0;");
        }
        __syncthreads();

#pragma unroll
        for (int ksub = 0; ksub < 4; ++ksub) {
            // B fragments for all 8 n-tiles (raw bits, operands pre-rounded)
            uint32_t bf[8][2];
#pragma unroll
            for (int nt = 0; nt < 8; nt++) {
                if (BNT) {
                    int n = warp_n * 64 + nt * 8 + (lane >> 2);
                    int base = s * 4096 + n * 32;
                    int c0 = ((ksub * 2) ^ (n & 7)) * 4 + (lane & 3);
                    int c1 = ((ksub * 2 + 1) ^ (n & 7)) * 4 + (lane & 3);
                    bf[nt][0] = __float_as_uint(Bs[base + c0]);
                    bf[nt][1] = __float_as_uint(Bs[base + c1]);
                } else {
                    int k = ksub * 8 + (lane & 3);
                    int n = warp_n * 64 + nt * 8 + (lane >> 2);
                    int off = s * 4096 + k * 128 +
                              (((n >> 2) ^ ((k & 3) * 2)) * 4) + (n & 3);
                    bf[nt][0] = __float_as_uint(Bs[off]);
                    bf[nt][1] = __float_as_uint(Bs[off + 512]);  // k+4 row
                }
            }
            // A fragments, 4 m-tiles of 16 rows
#pragma unroll
            for (int mt = 0; mt < 4; mt++) {
                int m = warp_m * 64 + mt * 16 + (lane >> 2);
                int base = s * 4096 + m * 32;
                int c0 = ((ksub * 2) ^ (m & 7)) * 4 + (lane & 3);
                int c1 = ((ksub * 2 + 1) ^ (m & 7)) * 4 + (lane & 3);
                uint32_t a0 = __float_as_uint(As[base + c0]);
                uint32_t a1 = __float_as_uint(As[base + 256 + c0]);   // m+8
                uint32_t a2 = __float_as_uint(As[base + c1]);
                uint32_t a3 = __float_as_uint(As[base + 256 + c1]);
#pragma unroll
                for (int nt = 0; nt < 8; nt++)
                    mma_tf32(acc[mt][nt], a0, a1, a2, a3, bf[nt][0], bf[nt][1]);
            }
        }
        __syncthreads();
    }

    // ---- epilogue ----
#pragma unroll
    for (int mt = 0; mt < 4; mt++) {
        int r0 = m0 + warp_m * 64 + mt * 16 + (lane >> 2);
#pragma unroll
        for (int nt = 0; nt < 8; nt++) {
            int cc = n0 + warp_n * 64 + nt * 8 + (lane & 3) * 2;
            float v0 = acc[mt][nt][0], v1 = acc[mt][nt][1];
            float v2 = acc[mt][nt][2], v3 = acc[mt][nt][3];
            if (EPI == 0) {
                v0 *= alpha; v1 *= alpha; v2 *= alpha; v3 *= alpha;
            } else if (EPI == 1) {
                const float2 ra = *(const float2*)(Rb + (long long)r0 * N + cc);
                const float2 rb = *(const float2*)(Rb + (long long)(r0 + 8) * N + cc);
                v0 += ra.x; v1 += ra.y; v2 += rb.x; v3 += rb.y;
            } else if (EPI == 2) {
                const float2 bb = *(const float2*)(bias + cc);
                v0 = roundtf(fmaxf(v0 + bb.x, 0.f));
                v1 = roundtf(fmaxf(v1 + bb.y, 0.f));
                v2 = roundtf(fmaxf(v2 + bb.x, 0.f));
                v3 = roundtf(fmaxf(v3 + bb.y, 0.f));
            } else {
                const float2 bb = *(const float2*)(bias + cc);
                const float2 ra = *(const float2*)(Rb + (long long)r0 * N + cc);
                const float2 rb = *(const float2*)(Rb + (long long)(r0 + 8) * N + cc);
                v0 += bb.x + ra.x; v1 += bb.y + ra.y;
                v2 += bb.x + rb.x; v3 += bb.y + rb.y;
            }
            *(float2*)(Cb + (long long)r0 * N + cc) = make_float2(v0, v1);
            *(float2*)(Cb + (long long)(r0 + 8) * N + cc) = make_float2(v2, v3);
        }
    }
}

// ---------------------------------------------------------------------------
// Row softmax over U=2048. One CTA (256 threads) per row, in place.
// Output is tf32-rounded (P feeds only the PV GEMM).
// ---------------------------------------------------------------------------
__global__ void softmax_rows(float* __restrict__ S)
{
    float* p = S + (long long)blockIdx.x * U_;
    const int tid = threadIdx.x;
    const int lane = tid & 31;
    const int wid = tid >> 5;
    __shared__ float red[8];

    float4 v0 = ((const float4*)p)[tid];
    float4 v1 = ((const float4*)p)[tid + 256];

    float m = fmaxf(fmaxf(fmaxf(v0.x, v0.y), fmaxf(v0.z, v0.w)),
                    fmaxf(fmaxf(v1.x, v1.y), fmaxf(v1.z, v1.w)));
#pragma unroll
    for (int o = 16; o > 0; o >>= 1) m = fmaxf(m, __shfl_xor_sync(0xffffffffu, m, o));
    if (lane == 0) red[wid] = m;
    __syncthreads();
    if (tid == 0) {
        float t = red[0];
#pragma unroll
        for (int i = 1; i < 8; i++) t = fmaxf(t, red[i]);
        red[0] = t;
    }
    __syncthreads();
    m = red[0];
    __syncthreads();

    v0.x = __expf(v0.x - m); v0.y = __expf(v0.y - m);
    v0.z = __expf(v0.z - m); v0.w = __expf(v0.w - m);
    v1.x = __expf(v1.x - m); v1.y = __expf(v1.y - m);
    v1.z = __expf(v1.z - m); v1.w = __expf(v1.w - m);
    float sum = v0.x + v0.y + v0.z + v0.w + v1.x + v1.y + v1.z + v1.w;
#pragma unroll
    for (int o = 16; o > 0; o >>= 1) sum += __shfl_xor_sync(0xffffffffu, sum, o);
    if (lane == 0) red[wid] = sum;
    __syncthreads();
    if (tid == 0) {
        float t = 0.f;
#pragma unroll
        for (int i = 0; i < 8; i++) t += red[i];
        red[0] = t;
    }
    __syncthreads();
    const float inv = 1.f / red[0];

    v0.x = roundtf(v0.x * inv); v0.y = roundtf(v0.y * inv);
    v0.z = roundtf(v0.z * inv); v0.w = roundtf(v0.w * inv);
    v1.x = roundtf(v1.x * inv); v1.y = roundtf(v1.y * inv);
    v1.z = roundtf(v1.z * inv); v1.w = roundtf(v1.w * inv);
    ((float4*)p)[tid] = v0;
    ((float4*)p)[tid + 256] = v1;
}

// ---------------------------------------------------------------------------
// Row LayerNorm over D=1024. One CTA (256 threads) per row. Two-pass stats.
// Optionally also writes a tf32-rounded copy (for GEMM A operand).
// ---------------------------------------------------------------------------
__global__ void layernorm_rows(const float* __restrict__ in, float* __restrict__ out,
                               float* __restrict__ out_r,
                               const float* __restrict__ gamma,
                               const float* __restrict__ beta)
{
    const long long row = (long long)blockIdx.x * D_;
    const int tid = threadIdx.x;
    const int lane = tid & 31;
    const int wid = tid >> 5;
    __shared__ float red[8];

    float4 v = ((const float4*)(in + row))[tid];

    float s = v.x + v.y + v.z + v.w;
#pragma unroll
    for (int o = 16; o > 0; o >>= 1) s += __shfl_xor_sync(0xffffffffu, s, o);
    if (lane == 0) red[wid] = s;
    __syncthreads();
    if (tid == 0) {
        float t = 0.f;
#pragma unroll
        for (int i = 0; i < 8; i++) t += red[i];
        red[0] = t;
    }
    __syncthreads();
    const float mean = red[0] * (1.f / D_);
    __syncthreads();

    float dx = v.x - mean, dy = v.y - mean, dz = v.z - mean, dw = v.w - mean;
    float sq = dx * dx + dy * dy + dz * dz + dw * dw;
#pragma unroll
    for (int o = 16; o > 0; o >>= 1) sq += __shfl_xor_sync(0xffffffffu, sq, o);
    if (lane == 0) red[wid] = sq;
    __syncthreads();
    if (tid == 0) {
        float t = 0.f;
#pragma unroll
        for (int i = 0; i < 8; i++) t += red[i];
        red[0] = t;
    }
    __syncthreads();
    const float var = red[0] * (1.f / D_);
    const float rstd = rsqrtf(var + 1e-6f);

    float4 g = ((const float4*)gamma)[tid];
    float4 bt = ((const float4*)beta)[tid];
    float4 o;
    o.x = dx * rstd * g.x + bt.x;
    o.y = dy * rstd * g.y + bt.y;
    o.z = dz * rstd * g.z + bt.z;
    o.w = dw * rstd * g.w + bt.w;
    ((float4*)(out + row))[tid] = o;
    if (out_r) {
        float4 r;
        r.x = roundtf(o.x); r.y = roundtf(o.y);
        r.z = roundtf(o.z); r.w = roundtf(o.w);
        ((float4*)(out_r + row))[tid] = r;
    }
}

// ---------------------------------------------------------------------------
// Launch
// ---------------------------------------------------------------------------
extern "C" void kernel_launch(void* const* d_in, const int* in_sizes, int n_in,
                              void* d_out, int out_size)
{
    const float* Q     = (const float*)d_in[0];
    const float* Kin   = (const float*)d_in[1];
    const float* V     = (const float*)d_in[2];
    const float* W1    = (const float*)d_in[3];
    const float* b1    = (const float*)d_in[4];
    const float* W2    = (const float*)d_in[5];
    const float* b2    = (const float*)d_in[6];
    const float* gamma = (const float*)d_in[7];
    const float* beta  = (const float*)d_in[8];
    float* out = (float*)d_out;

    float *S, *T, *X, *Xr, *H, *Qr, *Kr, *Vr, *W1r, *W2r;
    cudaGetSymbolAddress((void**)&S, g_S);
    cudaGetSymbolAddress((void**)&T, g_T);
    cudaGetSymbolAddress((void**)&X, g_X);
    cudaGetSymbolAddress((void**)&Xr, g_Xr);
    cudaGetSymbolAddress((void**)&H, g_H);
    cudaGetSymbolAddress((void**)&Qr, g_Qr);
    cudaGetSymbolAddress((void**)&Kr, g_Kr);
    cudaGetSymbolAddress((void**)&Vr, g_Vr);
    cudaGetSymbolAddress((void**)&W1r, g_W1r);
    cudaGetSymbolAddress((void**)&W2r, g_W2r);

    const float alpha = 1.0f / sqrtf((float)D_ + 1e-8f);
    const size_t shm = 65536;  // 2-stage * (16KB A + 16KB B)
    dim3 blk(128);

    cudaFuncSetAttribute(gemm_tf32<1, 0>, cudaFuncAttributeMaxDynamicSharedMemorySize, (int)shm);
    cudaFuncSetAttribute(gemm_tf32<0, 1>, cudaFuncAttributeMaxDynamicSharedMemorySize, (int)shm);
    cudaFuncSetAttribute(gemm_tf32<0, 2>, cudaFuncAttributeMaxDynamicSharedMemorySize, (int)shm);
    cudaFuncSetAttribute(gemm_tf32<0, 3>, cudaFuncAttributeMaxDynamicSharedMemorySize, (int)shm);

    // 0) pre-round operands to tf32 (one cvt per element, GEMMs use raw bits)
    const int QKV_BLOCKS = (B_ * R_ * D_) / (256 * 4);   // 32768
    round_tf32_kernel<<<QKV_BLOCKS, 256>>>(Q, Qr);
    round_tf32_kernel<<<QKV_BLOCKS, 256>>>(Kin, Kr);
    round_tf32_kernel<<<QKV_BLOCKS, 256>>>(V, Vr);
    round_tf32_kernel<<<(D_ * D_) / (256 * 4), 256>>>(W1, W1r);
    round_tf32_kernel<<<(D_ * D_) / (256 * 4), 256>>>(W2, W2r);

    // 1) S = Qr @ Kr^T / scale   (batched NT)
    gemm_tf32<1, 0><<<dim3(U_ / 128, R_ / 128, B_), blk, shm>>>(
        Qr, Kr, S, nullptr, nullptr, R_, U_, D_, D_, D_,
        (long long)R_ * D_, (long long)U_ * D_, (long long)R_ * U_, 0, alpha);

    // 2) softmax rows (writes tf32-rounded P)
    softmax_rows<<<B_ * R_, 256>>>(S);

    // 3) T = P @ Vr + Q   (batched NN, residual epilogue with full-precision Q)
    gemm_tf32<0, 1><<<dim3(D_ / 128, R_ / 128, B_), blk, shm>>>(
        S, Vr, T, Q, nullptr, R_, D_, U_, U_, D_,
        (long long)R_ * U_, (long long)U_ * D_, (long long)R_ * D_, (long long)R_ * D_, 1.f);

    // 4) X = LN(T)  (full X for residual, rounded Xr for FFN1)
    layernorm_rows<<<B_ * R_, 256>>>(T, X, Xr, gamma, beta);

    // 5) H = roundtf(relu(Xr @ W1r + b1))
    gemm_tf32<0, 2><<<dim3(D_ / 128, (B_ * R_) / 128, 1), blk, shm>>>(
        Xr, W1r, H, nullptr, b1, B_ * R_, D_, D_, D_, D_, 0, 0, 0, 0, 1.f);

    // 6) T = H @ W2r + b2 + X
    gemm_tf32<0, 3><<<dim3(D_ / 128, (B_ * R_) / 128, 1), blk, shm>>>(
        H, W2r, T, X, b2, B_ * R_, D_, D_, D_, D_, 0, 0, 0, 0, 1.f);

    // 7) out = LN(T)
    layernorm_rows<<<B_ * R_, 256>>>(T, out, nullptr, gamma, beta);
}

// round 9
// speedup vs baseline: 6.2596x; 1.8067x over previous
#include <cuda_runtime.h>
#include <cuda_fp16.h>
#include <math.h>
#include <stdint.h>

// Problem constants (fixed by the reference: B=16, R=2048, U=2048, D=1024)
#define B_ 16
#define R_ 2048
#define U_ 2048
#define D_ 1024

// Scratch (device globals: allocation-guard safe)
__device__ __align__(128) float  g_S[(size_t)B_ * R_ * U_];    // scores fp32 (256 MiB)
__device__ __align__(128) __half g_Ph[(size_t)B_ * R_ * U_];   // probs fp16 (128 MiB)
__device__ __align__(128) float  g_T[(size_t)B_ * R_ * D_];    // pre-LN buffer fp32
__device__ __align__(128) float  g_X[(size_t)B_ * R_ * D_];    // LN1 out fp32 (residual)
__device__ __align__(128) __half g_Xh[(size_t)B_ * R_ * D_];   // LN1 out fp16 (GEMM A)
__device__ __align__(128) __half g_Hh[(size_t)B_ * R_ * D_];   // FFN hidden fp16
__device__ __align__(128) __half g_Qh[(size_t)B_ * R_ * D_];   // fp16 Q
__device__ __align__(128) __half g_Kh[(size_t)B_ * U_ * D_];   // fp16 K
__device__ __align__(128) __half g_Vt[(size_t)B_ * D_ * U_];   // fp16 V^T [b][d][u]
__device__ __align__(128) __half g_W1t[(size_t)D_ * D_];       // fp16 W1^T
__device__ __align__(128) __half g_W2t[(size_t)D_ * D_];       // fp16 W2^T

// ---------------------------------------------------------------------------
// Helpers
// ---------------------------------------------------------------------------
__device__ __forceinline__ void mma_f16(float* c, uint32_t a0, uint32_t a1,
                                        uint32_t a2, uint32_t a3,
                                        uint32_t b0, uint32_t b1) {
    asm volatile(
        "mma.sync.aligned.m16n8k16.row.col.f32.f16.f16.f32 "
        "{%0,%1,%2,%3}, {%4,%5,%6,%7}, {%8,%9}, {%0,%1,%2,%3};"
        : "+f"(c[0]), "+f"(c[1]), "+f"(c[2]), "+f"(c[3])
        : "r"(a0), "r"(a1), "r"(a2), "r"(a3), "r"(b0), "r"(b1));
}

__device__ __forceinline__ void ldsm_x4(uint32_t& r0, uint32_t& r1,
                                        uint32_t& r2, uint32_t& r3, uint32_t addr) {
    asm volatile("ldmatrix.sync.aligned.m8n8.x4.shared.b16 {%0,%1,%2,%3}, [%4];"
                 : "=r"(r0), "=r"(r1), "=r"(r2), "=r"(r3) : "r"(addr));
}

__device__ __forceinline__ void cp16(uint32_t dst_smem, const void* src) {
    asm volatile("cp.async.cg.shared.global [%0], [%1], 16;" :: "r"(dst_smem), "l"(src));
}
__device__ __forceinline__ void cp_commit() { asm volatile("cp.async.commit_group;"); }

// ---------------------------------------------------------------------------
// fp32 -> fp16 elementwise convert
// ---------------------------------------------------------------------------
__global__ void f2h_kernel(const float* __restrict__ in, __half* __restrict__ out)
{
    long long i = (long long)blockIdx.x * 256 + threadIdx.x;
    float4 v = ((const float4*)in)[i];
    __half2 h0 = __floats2half2_rn(v.x, v.y);
    __half2 h1 = __floats2half2_rn(v.z, v.w);
    uint2 u;
    u.x = *(uint32_t*)&h0;
    u.y = *(uint32_t*)&h1;
    ((uint2*)out)[i] = u;
}

// ---------------------------------------------------------------------------
// Fused fp16-convert + transpose: out[c][r] = half(in[r][c]), per batch z.
// Block (32,8), tile 32x32.
// ---------------------------------------------------------------------------
__global__ void transTh_kernel(const float* __restrict__ in, __half* __restrict__ out,
                               int rows, int cols, long long sIn, long long sOut)
{
    __shared__ float t[32][33];
    const float* ib = in + (long long)blockIdx.z * sIn;
    __half* ob = out + (long long)blockIdx.z * sOut;
    int r0 = blockIdx.y * 32, c0 = blockIdx.x * 32;
#pragma unroll
    for (int i = 0; i < 4; i++) {
        int r = threadIdx.y + i * 8;
        t[r][threadIdx.x] = ib[(long long)(r0 + r) * cols + c0 + threadIdx.x];
    }
    __syncthreads();
#pragma unroll
    for (int i = 0; i < 4; i++) {
        int r = threadIdx.y + i * 8;
        ob[(long long)(c0 + r) * rows + r0 + threadIdx.x] = __float2half_rn(t[threadIdx.x][r]);
    }
}

// ---------------------------------------------------------------------------
// fp16 NT GEMM via mma.sync.m16n8k16 + ldmatrix.
// C[b][m][n] = epi( sum_k A[b][m][k] * B[b][n][k] ),  A:[M,K] B:[N,K] half.
// CTA tile 128x128, KTILE=64, 2-stage cp.async, 128 threads (4 warps, 64x64).
// Smem per stage: A 128x64h (16KB) + B 128x64h (16KB); rows are 128B, SW128
// swizzle: byte = r*128 + ((c16 ^ (r&7))<<4) + within16.
// EPI 0: S = alpha*acc (fp32)        EPI 1: C = acc + res (fp32)
// EPI 2: Ch = half(relu(acc+bias))   EPI 3: C = acc + bias + res (fp32)
// ---------------------------------------------------------------------------
template <int EPI>
__global__ __launch_bounds__(128)
void gemm_h(const __half* __restrict__ A, const __half* __restrict__ Bm,
            float* __restrict__ C, __half* __restrict__ Ch,
            const float* __restrict__ res, const float* __restrict__ bias,
            int M, int N, int K, int lda, int ldb,
            long long sA, long long sB, long long sC, long long sRes,
            float alpha)
{
    extern __shared__ char smc[];
    uint32_t sm_u = (uint32_t)__cvta_generic_to_shared(smc);
    // stage s: A at s*16384, B at 32768 + s*16384  (bytes)

    const __half* Ab = A + (long long)blockIdx.z * sA;
    const __half* Bb = Bm + (long long)blockIdx.z * sB;
    float*        Cb = C ? (C + (long long)blockIdx.z * sC) : C;
    __half*       Chb = Ch ? (Ch + (long long)blockIdx.z * sC) : Ch;
    const float*  Rb = res ? (res + (long long)blockIdx.z * sRes) : res;

    const int m0 = blockIdx.y * 128;
    const int n0 = blockIdx.x * 128;
    const int tid = threadIdx.x;
    const int lane = tid & 31;
    const int wid = tid >> 5;
    const int warp_m = wid & 1;   // 2 warps along M (64 rows)
    const int warp_n = wid >> 1;  // 2 warps along N (64 cols)

    float acc[4][8][4];
#pragma unroll
    for (int i = 0; i < 4; i++)
#pragma unroll
        for (int j = 0; j < 8; j++)
#pragma unroll
            for (int l = 0; l < 4; l++) acc[i][j][l] = 0.f;

    const int KT = K >> 6;  // K / 64

    auto prefetch = [&](int kt, int s) {
#pragma unroll
        for (int i = 0; i < 8; i++) {          // A: 1024 16B chunks
            int idx = tid + i * 128;
            int r = idx >> 3, c = idx & 7;     // row 0..127, 16B chunk 0..7
            cp16(sm_u + (uint32_t)(s * 16384 + r * 128 + ((c ^ (r & 7)) << 4)),
                 Ab + (long long)(m0 + r) * lda + kt * 64 + c * 8);
        }
#pragma unroll
        for (int i = 0; i < 8; i++) {          // B: 1024 16B chunks
            int idx = tid + i * 128;
            int r = idx >> 3, c = idx & 7;
            cp16(sm_u + (uint32_t)(32768 + s * 16384 + r * 128 + ((c ^ (r & 7)) << 4)),
                 Bb + (long long)(n0 + r) * ldb + kt * 64 + c * 8);
        }
        cp_commit();
    };

    prefetch(0, 0);

    for (int kt = 0; kt < KT; ++kt) {
        const int s = kt & 1;
        if (kt + 1 < KT) {
            prefetch(kt + 1, (kt + 1) & 1);
            asm volatile("cp.async.wait_group 1;");
        } else {
            asm volatile("cp.async.wait_group 0;");
        }
        __syncthreads();

#pragma unroll
        for (int ksub = 0; ksub < 4; ++ksub) {
            // B fragments: 4 x ldmatrix.x4 covering 8 n-tiles
            uint32_t bf[8][2];
#pragma unroll
            for (int p = 0; p < 4; p++) {
                int n = warp_n * 64 + p * 16 + ((lane >> 4) * 8) + (lane & 7);
                int kh = ksub * 16 + ((lane >> 3) & 1) * 8;
                uint32_t addr = sm_u + 32768 + s * 16384 + n * 128 +
                                ((((kh >> 3) ^ (n & 7))) << 4);
                ldsm_x4(bf[2 * p][0], bf[2 * p][1], bf[2 * p + 1][0], bf[2 * p + 1][1], addr);
            }
            // A fragments + MMAs, 4 m-tiles of 16 rows
#pragma unroll
            for (int mt = 0; mt < 4; mt++) {
                int row = warp_m * 64 + mt * 16 + (lane & 15);
                int kh = ksub * 16 + (lane >> 4) * 8;
                uint32_t addr = sm_u + s * 16384 + row * 128 +
                                ((((kh >> 3) ^ (row & 7))) << 4);
                uint32_t a0, a1, a2, a3;
                ldsm_x4(a0, a1, a2, a3, addr);
#pragma unroll
                for (int nt = 0; nt < 8; nt++)
                    mma_f16(acc[mt][nt], a0, a1, a2, a3, bf[nt][0], bf[nt][1]);
            }
        }
        __syncthreads();
    }

    // ---- epilogue ----
#pragma unroll
    for (int mt = 0; mt < 4; mt++) {
        int r0 = m0 + warp_m * 64 + mt * 16 + (lane >> 2);
#pragma unroll
        for (int nt = 0; nt < 8; nt++) {
            int cc = n0 + warp_n * 64 + nt * 8 + (lane & 3) * 2;
            float v0 = acc[mt][nt][0], v1 = acc[mt][nt][1];
            float v2 = acc[mt][nt][2], v3 = acc[mt][nt][3];
            if (EPI == 0) {
                v0 *= alpha; v1 *= alpha; v2 *= alpha; v3 *= alpha;
                *(float2*)(Cb + (long long)r0 * N + cc) = make_float2(v0, v1);
                *(float2*)(Cb + (long long)(r0 + 8) * N + cc) = make_float2(v2, v3);
            } else if (EPI == 1) {
                const float2 ra = *(const float2*)(Rb + (long long)r0 * N + cc);
                const float2 rb = *(const float2*)(Rb + (long long)(r0 + 8) * N + cc);
                *(float2*)(Cb + (long long)r0 * N + cc) = make_float2(v0 + ra.x, v1 + ra.y);
                *(float2*)(Cb + (long long)(r0 + 8) * N + cc) = make_float2(v2 + rb.x, v3 + rb.y);
            } else if (EPI == 2) {
                const float2 bb = *(const float2*)(bias + cc);
                __half2 h0 = __floats2half2_rn(fmaxf(v0 + bb.x, 0.f), fmaxf(v1 + bb.y, 0.f));
                __half2 h1 = __floats2half2_rn(fmaxf(v2 + bb.x, 0.f), fmaxf(v3 + bb.y, 0.f));
                *(__half2*)(Chb + (long long)r0 * N + cc) = h0;
                *(__half2*)(Chb + (long long)(r0 + 8) * N + cc) = h1;
            } else {
                const float2 bb = *(const float2*)(bias + cc);
                const float2 ra = *(const float2*)(Rb + (long long)r0 * N + cc);
                const float2 rb = *(const float2*)(Rb + (long long)(r0 + 8) * N + cc);
                *(float2*)(Cb + (long long)r0 * N + cc) =
                    make_float2(v0 + bb.x + ra.x, v1 + bb.y + ra.y);
                *(float2*)(Cb + (long long)(r0 + 8) * N + cc) =
                    make_float2(v2 + bb.x + rb.x, v3 + bb.y + rb.y);
            }
        }
    }
}

// ---------------------------------------------------------------------------
// Row softmax over U=2048 (fp32 in), writes fp16 probs. One CTA per row.
// ---------------------------------------------------------------------------
__global__ void softmax_rows(const float* __restrict__ S, __half* __restrict__ P)
{
    const float* p = S + (long long)blockIdx.x * U_;
    __half* q = P + (long long)blockIdx.x * U_;
    const int tid = threadIdx.x;
    const int lane = tid & 31;
    const int wid = tid >> 5;
    __shared__ float red[8];

    float4 v0 = ((const float4*)p)[tid];
    float4 v1 = ((const float4*)p)[tid + 256];

    float m = fmaxf(fmaxf(fmaxf(v0.x, v0.y), fmaxf(v0.z, v0.w)),
                    fmaxf(fmaxf(v1.x, v1.y), fmaxf(v1.z, v1.w)));
#pragma unroll
    for (int o = 16; o > 0; o >>= 1) m = fmaxf(m, __shfl_xor_sync(0xffffffffu, m, o));
    if (lane == 0) red[wid] = m;
    __syncthreads();
    if (tid == 0) {
        float t = red[0];
#pragma unroll
        for (int i = 1; i < 8; i++) t = fmaxf(t, red[i]);
        red[0] = t;
    }
    __syncthreads();
    m = red[0];
    __syncthreads();

    v0.x = __expf(v0.x - m); v0.y = __expf(v0.y - m);
    v0.z = __expf(v0.z - m); v0.w = __expf(v0.w - m);
    v1.x = __expf(v1.x - m); v1.y = __expf(v1.y - m);
    v1.z = __expf(v1.z - m); v1.w = __expf(v1.w - m);
    float sum = v0.x + v0.y + v0.z + v0.w + v1.x + v1.y + v1.z + v1.w;
#pragma unroll
    for (int o = 16; o > 0; o >>= 1) sum += __shfl_xor_sync(0xffffffffu, sum, o);
    if (lane == 0) red[wid] = sum;
    __syncthreads();
    if (tid == 0) {
        float t = 0.f;
#pragma unroll
        for (int i = 0; i < 8; i++) t += red[i];
        red[0] = t;
    }
    __syncthreads();
    const float inv = 1.f / red[0];

    __half2 h0 = __floats2half2_rn(v0.x * inv, v0.y * inv);
    __half2 h1 = __floats2half2_rn(v0.z * inv, v0.w * inv);
    __half2 h2 = __floats2half2_rn(v1.x * inv, v1.y * inv);
    __half2 h3 = __floats2half2_rn(v1.z * inv, v1.w * inv);
    uint2 u0, u1;
    u0.x = *(uint32_t*)&h0; u0.y = *(uint32_t*)&h1;
    u1.x = *(uint32_t*)&h2; u1.y = *(uint32_t*)&h3;
    ((uint2*)q)[tid] = u0;
    ((uint2*)q)[tid + 256] = u1;
}

// ---------------------------------------------------------------------------
// Row LayerNorm over D=1024. Two-pass stats. Optional fp16 copy.
// ---------------------------------------------------------------------------
__global__ void layernorm_rows(const float* __restrict__ in, float* __restrict__ out,
                               __half* __restrict__ out_h,
                               const float* __restrict__ gamma,
                               const float* __restrict__ beta)
{
    const long long row = (long long)blockIdx.x * D_;
    const int tid = threadIdx.x;
    const int lane = tid & 31;
    const int wid = tid >> 5;
    __shared__ float red[8];

    float4 v = ((const float4*)(in + row))[tid];

    float s = v.x + v.y + v.z + v.w;
#pragma unroll
    for (int o = 16; o > 0; o >>= 1) s += __shfl_xor_sync(0xffffffffu, s, o);
    if (lane == 0) red[wid] = s;
    __syncthreads();
    if (tid == 0) {
        float t = 0.f;
#pragma unroll
        for (int i = 0; i < 8; i++) t += red[i];
        red[0] = t;
    }
    __syncthreads();
    const float mean = red[0] * (1.f / D_);
    __syncthreads();

    float dx = v.x - mean, dy = v.y - mean, dz = v.z - mean, dw = v.w - mean;
    float sq = dx * dx + dy * dy + dz * dz + dw * dw;
#pragma unroll
    for (int o = 16; o > 0; o >>= 1) sq += __shfl_xor_sync(0xffffffffu, sq, o);
    if (lane == 0) red[wid] = sq;
    __syncthreads();
    if (tid == 0) {
        float t = 0.f;
#pragma unroll
        for (int i = 0; i < 8; i++) t += red[i];
        red[0] = t;
    }
    __syncthreads();
    const float var = red[0] * (1.f / D_);
    const float rstd = rsqrtf(var + 1e-6f);

    float4 g = ((const float4*)gamma)[tid];
    float4 bt = ((const float4*)beta)[tid];
    float4 o;
    o.x = dx * rstd * g.x + bt.x;
    o.y = dy * rstd * g.y + bt.y;
    o.z = dz * rstd * g.z + bt.z;
    o.w = dw * rstd * g.w + bt.w;
    ((float4*)(out + row))[tid] = o;
    if (out_h) {
        __half2 h0 = __floats2half2_rn(o.x, o.y);
        __half2 h1 = __floats2half2_rn(o.z, o.w);
        uint2 u;
        u.x = *(uint32_t*)&h0; u.y = *(uint32_t*)&h1;
        ((uint2*)(out_h + row))[tid] = u;
    }
}

// ---------------------------------------------------------------------------
// Launch
// ---------------------------------------------------------------------------
extern "C" void kernel_launch(void* const* d_in, const int* in_sizes, int n_in,
                              void* d_out, int out_size)
{
    const float* Q     = (const float*)d_in[0];
    const float* Kin   = (const float*)d_in[1];
    const float* V     = (const float*)d_in[2];
    const float* W1    = (const float*)d_in[3];
    const float* b1    = (const float*)d_in[4];
    const float* W2    = (const float*)d_in[5];
    const float* b2    = (const float*)d_in[6];
    const float* gamma = (const float*)d_in[7];
    const float* beta  = (const float*)d_in[8];
    float* out = (float*)d_out;

    float *S, *T, *X;
    __half *Ph, *Xh, *Hh, *Qh, *Kh, *Vt, *W1t, *W2t;
    cudaGetSymbolAddress((void**)&S, g_S);
    cudaGetSymbolAddress((void**)&T, g_T);
    cudaGetSymbolAddress((void**)&X, g_X);
    cudaGetSymbolAddress((void**)&Ph, g_Ph);
    cudaGetSymbolAddress((void**)&Xh, g_Xh);
    cudaGetSymbolAddress((void**)&Hh, g_Hh);
    cudaGetSymbolAddress((void**)&Qh, g_Qh);
    cudaGetSymbolAddress((void**)&Kh, g_Kh);
    cudaGetSymbolAddress((void**)&Vt, g_Vt);
    cudaGetSymbolAddress((void**)&W1t, g_W1t);
    cudaGetSymbolAddress((void**)&W2t, g_W2t);

    const float alpha = 1.0f / sqrtf((float)D_ + 1e-8f);
    const int shm = 65536;  // 2 stages x (16KB A + 16KB B)
    dim3 blk(128);

    cudaFuncSetAttribute(gemm_h<0>, cudaFuncAttributeMaxDynamicSharedMemorySize, shm);
    cudaFuncSetAttribute(gemm_h<1>, cudaFuncAttributeMaxDynamicSharedMemorySize, shm);
    cudaFuncSetAttribute(gemm_h<2>, cudaFuncAttributeMaxDynamicSharedMemorySize, shm);
    cudaFuncSetAttribute(gemm_h<3>, cudaFuncAttributeMaxDynamicSharedMemorySize, shm);

    // 0) convert operands to fp16 (Q,K plain; V,W1,W2 transposed so all GEMMs are NT)
    const int QKV_BLOCKS = (B_ * R_ * D_) / (256 * 4);
    f2h_kernel<<<QKV_BLOCKS, 256>>>(Q, Qh);
    f2h_kernel<<<QKV_BLOCKS, 256>>>(Kin, Kh);
    transTh_kernel<<<dim3(D_ / 32, U_ / 32, B_), dim3(32, 8)>>>(
        V, Vt, U_, D_, (long long)U_ * D_, (long long)D_ * U_);
    transTh_kernel<<<dim3(D_ / 32, D_ / 32, 1), dim3(32, 8)>>>(W1, W1t, D_, D_, 0, 0);
    transTh_kernel<<<dim3(D_ / 32, D_ / 32, 1), dim3(32, 8)>>>(W2, W2t, D_, D_, 0, 0);

    // 1) S = Qh @ Kh^T / scale  (fp32 out)
    gemm_h<0><<<dim3(U_ / 128, R_ / 128, B_), blk, shm>>>(
        Qh, Kh, S, nullptr, nullptr, nullptr, R_, U_, D_, D_, D_,
        (long long)R_ * D_, (long long)U_ * D_, (long long)R_ * U_, 0, alpha);

    // 2) softmax rows -> fp16 P
    softmax_rows<<<B_ * R_, 256>>>(S, Ph);

    // 3) T = P @ Vt^T + Q  (fp32 out, fp32 Q residual)
    gemm_h<1><<<dim3(D_ / 128, R_ / 128, B_), blk, shm>>>(
        Ph, Vt, T, nullptr, Q, nullptr, R_, D_, U_, U_, U_,
        (long long)R_ * U_, (long long)D_ * U_, (long long)R_ * D_, (long long)R_ * D_, 1.f);

    // 4) X = LN(T)  (fp32 X for residual, fp16 Xh for FFN1)
    layernorm_rows<<<B_ * R_, 256>>>(T, X, Xh, gamma, beta);

    // 5) Hh = half(relu(Xh @ W1t^T + b1))
    gemm_h<2><<<dim3(D_ / 128, (B_ * R_) / 128, 1), blk, shm>>>(
        Xh, W1t, nullptr, Hh, nullptr, b1, B_ * R_, D_, D_, D_, D_, 0, 0, 0, 0, 1.f);

    // 6) T = Hh @ W2t^T + b2 + X
    gemm_h<3><<<dim3(D_ / 128, (B_ * R_) / 128, 1), blk, shm>>>(
        Hh, W2t, T, nullptr, X, b2, B_ * R_, D_, D_, D_, D_, 0, 0, 0, 0, 1.f);

    // 7) out = LN(T)
    layernorm_rows<<<B_ * R_, 256>>>(T, out, nullptr, gamma, beta);
}